// round 2
// baseline (speedup 1.0000x reference)
#include <cuda_runtime.h>
#include <math.h>

#define BB 8
#define CC 128
#define NPIX (512*512)          // pixels per batch image
#define SPLIT 16                // blocks per (b,c) plane in sum pass
#define CHUNK (NPIX/SPLIT)      // 16384 elements per block
#define EPSV 1e-12f

// ---- scratch (no allocations allowed) ----
__device__ float g_sumC[BB*CC];
__device__ float g_sumN[BB*CC];
__device__ int   g_cntC[BB];
__device__ int   g_cntN[BB];
__device__ float g_dvec[BB*CC];
__device__ float g_valid[BB];

// ---------------- zero accumulators ----------------
__global__ void k_zero() {
    int i = blockIdx.x * blockDim.x + threadIdx.x;
    if (i < BB*CC) { g_sumC[i] = 0.f; g_sumN[i] = 0.f; }
    if (i < BB)    { g_cntC[i] = 0;   g_cntN[i] = 0;   }
}

// ---------------- class counts per batch ----------------
__global__ void k_count(const int* __restrict__ gt) {
    int b = blockIdx.y;
    const int4* g4 = (const int4*)(gt + (size_t)b * NPIX);
    int stride = gridDim.x * blockDim.x;
    int cc = 0, cn = 0;
    for (int i = blockIdx.x * blockDim.x + threadIdx.x; i < NPIX/4; i += stride) {
        int4 g = g4[i];
        cc += (g.x==1) + (g.y==1) + (g.z==1) + (g.w==1);
        cn += (g.x==0) + (g.y==0) + (g.z==0) + (g.w==0);
    }
    #pragma unroll
    for (int o = 16; o; o >>= 1) {
        cc += __shfl_down_sync(0xffffffffu, cc, o);
        cn += __shfl_down_sync(0xffffffffu, cn, o);
    }
    __shared__ int sc[8], sn[8];
    int w = threadIdx.x >> 5;
    if ((threadIdx.x & 31) == 0) { sc[w] = cc; sn[w] = cn; }
    __syncthreads();
    if (threadIdx.x == 0) {
        int tc = 0, tn = 0;
        int nw = blockDim.x >> 5;
        for (int i = 0; i < nw; i++) { tc += sc[i]; tn += sn[i]; }
        atomicAdd(&g_cntC[b], tc);
        atomicAdd(&g_cntN[b], tn);
    }
}

// ---------------- masked channel sums ----------------
// grid: (SPLIT, CC, BB), 256 threads
__global__ void k_sums(const float* __restrict__ fm, const int* __restrict__ gt) {
    int chunk = blockIdx.x, c = blockIdx.y, b = blockIdx.z;
    const float4* f4 = (const float4*)(fm + ((size_t)(b*CC + c)) * NPIX + (size_t)chunk * CHUNK);
    const int4*   g4 = (const int4*)(gt + (size_t)b * NPIX + (size_t)chunk * CHUNK);
    float sc = 0.f, sn = 0.f;
    const int nvec = CHUNK / 4;  // 4096
    #pragma unroll 4
    for (int j = threadIdx.x; j < nvec; j += 256) {
        float4 v = f4[j];
        int4   g = g4[j];
        sc += (g.x==1 ? v.x : 0.f) + (g.y==1 ? v.y : 0.f) + (g.z==1 ? v.z : 0.f) + (g.w==1 ? v.w : 0.f);
        sn += (g.x==0 ? v.x : 0.f) + (g.y==0 ? v.y : 0.f) + (g.z==0 ? v.z : 0.f) + (g.w==0 ? v.w : 0.f);
    }
    #pragma unroll
    for (int o = 16; o; o >>= 1) {
        sc += __shfl_down_sync(0xffffffffu, sc, o);
        sn += __shfl_down_sync(0xffffffffu, sn, o);
    }
    __shared__ float shc[8], shn[8];
    int w = threadIdx.x >> 5;
    if ((threadIdx.x & 31) == 0) { shc[w] = sc; shn[w] = sn; }
    __syncthreads();
    if (threadIdx.x == 0) {
        float tc = 0.f, tn = 0.f;
        for (int i = 0; i < 8; i++) { tc += shc[i]; tn += shn[i]; }
        atomicAdd(&g_sumC[b*CC + c], tc);
        atomicAdd(&g_sumN[b*CC + c], tn);
    }
}

// ---------------- prototype normalize + difference vector ----------------
// grid: BB blocks, CC threads
__global__ void k_proto() {
    int b = blockIdx.x, c = threadIdx.x;
    float nc = (float)g_cntC[b];
    float nn = (float)g_cntN[b];
    float pc = g_sumC[b*CC + c] / fmaxf(nc, 1.f);
    float pn = g_sumN[b*CC + c] / fmaxf(nn, 1.f);
    float s1 = pc*pc, s2 = pn*pn;
    #pragma unroll
    for (int o = 16; o; o >>= 1) {
        s1 += __shfl_down_sync(0xffffffffu, s1, o);
        s2 += __shfl_down_sync(0xffffffffu, s2, o);
    }
    __shared__ float r1[4], r2[4];
    int w = c >> 5;
    if ((c & 31) == 0) { r1[w] = s1; r2[w] = s2; }
    __syncthreads();
    float t1 = r1[0] + r1[1] + r1[2] + r1[3];
    float t2 = r2[0] + r2[1] + r2[2] + r2[3];
    float npc = fmaxf(sqrtf(t1), EPSV);
    float npn = fmaxf(sqrtf(t2), EPSV);
    g_dvec[b*CC + c] = pc / npc - pn / npn;
    if (c == 0) g_valid[b] = (nc > 0.f && nn > 0.f) ? 1.f : 0.f;
}

// ---------------- per-pixel similarity + exp ----------------
// grid: (NPIX/1024, BB), 256 threads, each thread 4 pixels (float4)
__global__ void k_out(const float* __restrict__ fm, const int* __restrict__ gt,
                      float* __restrict__ out) {
    int b = blockIdx.y;
    __shared__ float sd[CC];
    __shared__ float sval;
    if (threadIdx.x < CC) sd[threadIdx.x] = g_dvec[b*CC + threadIdx.x];
    if (threadIdx.x == 0) sval = g_valid[b];
    __syncthreads();

    int base = blockIdx.x * 256 + threadIdx.x;          // float4 index within batch plane
    const float4* f4 = (const float4*)(fm + (size_t)b * CC * NPIX);
    const int4*   g4 = (const int4*)(gt + (size_t)b * NPIX);

    float4 s = {0.f,0.f,0.f,0.f};
    float4 q = {0.f,0.f,0.f,0.f};
    #pragma unroll 8
    for (int c = 0; c < CC; c++) {
        float4 v = f4[(size_t)c * (NPIX/4) + base];
        float dc = sd[c];
        s.x += v.x * dc;  q.x += v.x * v.x;
        s.y += v.y * dc;  q.y += v.y * v.y;
        s.z += v.z * dc;  q.z += v.z * v.z;
        s.w += v.w * dc;  q.w += v.w * v.w;
    }
    int4 g = g4[base];
    float val = sval;
    float4 o;
    o.x = val * expf(((g.x==1) ? 1.f : -1.f) * s.x / fmaxf(sqrtf(q.x), EPSV));
    o.y = val * expf(((g.y==1) ? 1.f : -1.f) * s.y / fmaxf(sqrtf(q.y), EPSV));
    o.z = val * expf(((g.z==1) ? 1.f : -1.f) * s.z / fmaxf(sqrtf(q.z), EPSV));
    o.w = val * expf(((g.w==1) ? 1.f : -1.f) * s.w / fmaxf(sqrtf(q.w), EPSV));
    ((float4*)(out + (size_t)b * NPIX))[base] = o;
}

extern "C" void kernel_launch(void* const* d_in, const int* in_sizes, int n_in,
                              void* d_out, int out_size) {
    const float* fm = (const float*)d_in[0];
    const int*   gt = (const int*)d_in[1];
    float* out = (float*)d_out;

    k_zero<<<(BB*CC + 255)/256, 256>>>();
    {
        dim3 grid(64, BB);
        k_count<<<grid, 256>>>(gt);
    }
    {
        dim3 grid(SPLIT, CC, BB);
        k_sums<<<grid, 256>>>(fm, gt);
    }
    k_proto<<<BB, CC>>>();
    {
        dim3 grid(NPIX/1024, BB);
        k_out<<<grid, 256>>>(fm, gt, out);
    }
}